// round 1
// baseline (speedup 1.0000x reference)
#include <cuda_runtime.h>
#include <math.h>

// ---------------- fixed problem shapes ----------------
#define TDIM 8
#define HDIM 24
#define WDIM 32
#define CDIM 2048
#define LT   128
#define NV   (TDIM*HDIM*WDIM)   // 6144 visual tokens
#define NTOK (NV+LT)            // 6272
#define HEADS 16
#define HD    128
#define GNUM  4                 // gt=1, gh=2, gw=2
#define LV    (NV/GNUM)         // 1536
#define LSEQ  (LV+LT)           // 1664
#define GH    (GNUM*HEADS)      // 64
#define EPSV  1e-6f
#define SCALE 0.08838834764831845f   // 1/sqrt(128)

// ---------------- scratch (device globals; no runtime allocs) ----------------
__device__ float g_x  [(size_t)NTOK*CDIM];
__device__ float g_q  [(size_t)NTOK*CDIM];
__device__ float g_k  [(size_t)NTOK*CDIM];
__device__ float g_v  [(size_t)NTOK*CDIM];
__device__ float g_Qp [(size_t)GH*LSEQ*HD];
__device__ float g_Kp [(size_t)GH*LSEQ*HD];
__device__ float g_Vp [(size_t)GH*LSEQ*HD];
__device__ float g_O  [(size_t)GH*LSEQ*HD];
__device__ float g_S  [(size_t)GH*LSEQ*LSEQ];   // 709 MB
__device__ float g_ctx[(size_t)NTOK*CDIM];

// ---------------- concat visual+text into one row-major matrix ----------------
__global__ void concat_kernel(const float* __restrict__ vis, const float* __restrict__ text)
{
    size_t i4 = (size_t)blockIdx.x * blockDim.x + threadIdx.x;   // float4 index
    size_t total4 = (size_t)NTOK * CDIM / 4;
    if (i4 >= total4) return;
    size_t nv4 = (size_t)NV * CDIM / 4;
    float4 v;
    if (i4 < nv4) v = ((const float4*)vis)[i4];
    else          v = ((const float4*)text)[i4 - nv4];
    ((float4*)g_x)[i4] = v;
}

// ---------------- SGEMM NT: C = alpha*A*B^T (+bias[n]) ----------------
// A [M,K] rm, B [N,K] rm, C [M,N] rm. M,N multiples of 128, K multiple of 16.
__global__ void __launch_bounds__(256)
sgemm_nt(const float* __restrict__ A, const float* __restrict__ B,
         const float* __restrict__ bias, float* __restrict__ C,
         int M, int N, int K, float alpha,
         long long sA, long long sB, long long sC)
{
    A += (long long)blockIdx.z * sA;
    B += (long long)blockIdx.z * sB;
    C += (long long)blockIdx.z * sC;

    __shared__ float As[16][128];
    __shared__ float Bs[16][128];

    int tid = threadIdx.x;
    int lr = tid >> 2;            // 0..63
    int lc = (tid & 3) << 2;      // 0,4,8,12
    int tx = tid & 15, ty = tid >> 4;

    const float* Ab = A + (size_t)blockIdx.y * 128 * K;
    const float* Bb = B + (size_t)blockIdx.x * 128 * K;

    float acc[8][8];
#pragma unroll
    for (int i = 0; i < 8; i++)
#pragma unroll
        for (int j = 0; j < 8; j++) acc[i][j] = 0.f;

    for (int k0 = 0; k0 < K; k0 += 16) {
#pragma unroll
        for (int r = 0; r < 2; r++) {
            int row = lr + r * 64;
            float4 va = *(const float4*)(Ab + (size_t)row * K + k0 + lc);
            As[lc+0][row] = va.x; As[lc+1][row] = va.y;
            As[lc+2][row] = va.z; As[lc+3][row] = va.w;
            float4 vb = *(const float4*)(Bb + (size_t)row * K + k0 + lc);
            Bs[lc+0][row] = vb.x; Bs[lc+1][row] = vb.y;
            Bs[lc+2][row] = vb.z; Bs[lc+3][row] = vb.w;
        }
        __syncthreads();
#pragma unroll
        for (int kk = 0; kk < 16; kk++) {
            float a[8], b[8];
            *(float4*)&a[0] = *(const float4*)&As[kk][ty*4];
            *(float4*)&a[4] = *(const float4*)&As[kk][64 + ty*4];
            *(float4*)&b[0] = *(const float4*)&Bs[kk][tx*4];
            *(float4*)&b[4] = *(const float4*)&Bs[kk][64 + tx*4];
#pragma unroll
            for (int i = 0; i < 8; i++)
#pragma unroll
                for (int j = 0; j < 8; j++)
                    acc[i][j] = fmaf(a[i], b[j], acc[i][j]);
        }
        __syncthreads();
    }

#pragma unroll
    for (int ri = 0; ri < 2; ri++)
#pragma unroll
        for (int i = 0; i < 4; i++) {
            int row = blockIdx.y * 128 + ri * 64 + ty * 4 + i;
#pragma unroll
            for (int cj = 0; cj < 2; cj++) {
                int col = blockIdx.x * 128 + cj * 64 + tx * 4;
                float4 o;
                o.x = alpha * acc[ri*4+i][cj*4+0];
                o.y = alpha * acc[ri*4+i][cj*4+1];
                o.z = alpha * acc[ri*4+i][cj*4+2];
                o.w = alpha * acc[ri*4+i][cj*4+3];
                if (bias) {
                    o.x += bias[col+0]; o.y += bias[col+1];
                    o.z += bias[col+2]; o.w += bias[col+3];
                }
                *(float4*)(C + (size_t)row * N + col) = o;
            }
        }
}

// ---------------- SGEMM NN: C = A*B ----------------
// A [M,K] rm, B [K,N] rm, C [M,N] rm. M,N multiples of 128 (N=128 here), K mult of 16.
__global__ void __launch_bounds__(256)
sgemm_nn(const float* __restrict__ A, const float* __restrict__ B,
         float* __restrict__ C,
         int M, int N, int K,
         long long sA, long long sB, long long sC)
{
    A += (long long)blockIdx.z * sA;
    B += (long long)blockIdx.z * sB;
    C += (long long)blockIdx.z * sC;

    __shared__ float As[16][128];
    __shared__ float Bs[16][128];

    int tid = threadIdx.x;
    int lr = tid >> 2;
    int lc = (tid & 3) << 2;
    int bc = (tid & 31) << 2;     // 0..124
    int br = tid >> 5;            // 0..7
    int tx = tid & 15, ty = tid >> 4;

    const float* Ab = A + (size_t)blockIdx.y * 128 * K;

    float acc[8][8];
#pragma unroll
    for (int i = 0; i < 8; i++)
#pragma unroll
        for (int j = 0; j < 8; j++) acc[i][j] = 0.f;

    for (int k0 = 0; k0 < K; k0 += 16) {
#pragma unroll
        for (int r = 0; r < 2; r++) {
            int row = lr + r * 64;
            float4 va = *(const float4*)(Ab + (size_t)row * K + k0 + lc);
            As[lc+0][row] = va.x; As[lc+1][row] = va.y;
            As[lc+2][row] = va.z; As[lc+3][row] = va.w;
            int kr = br + r * 8;
            float4 vb = *(const float4*)(B + (size_t)(k0 + kr) * N + blockIdx.x * 128 + bc);
            *(float4*)&Bs[kr][bc] = vb;
        }
        __syncthreads();
#pragma unroll
        for (int kk = 0; kk < 16; kk++) {
            float a[8], b[8];
            *(float4*)&a[0] = *(const float4*)&As[kk][ty*4];
            *(float4*)&a[4] = *(const float4*)&As[kk][64 + ty*4];
            *(float4*)&b[0] = *(const float4*)&Bs[kk][tx*4];
            *(float4*)&b[4] = *(const float4*)&Bs[kk][64 + tx*4];
#pragma unroll
            for (int i = 0; i < 8; i++)
#pragma unroll
                for (int j = 0; j < 8; j++)
                    acc[i][j] = fmaf(a[i], b[j], acc[i][j]);
        }
        __syncthreads();
    }

#pragma unroll
    for (int ri = 0; ri < 2; ri++)
#pragma unroll
        for (int i = 0; i < 4; i++) {
            int row = blockIdx.y * 128 + ri * 64 + ty * 4 + i;
#pragma unroll
            for (int cj = 0; cj < 2; cj++) {
                int col = blockIdx.x * 128 + cj * 64 + tx * 4;
                float4 o;
                o.x = acc[ri*4+i][cj*4+0];
                o.y = acc[ri*4+i][cj*4+1];
                o.z = acc[ri*4+i][cj*4+2];
                o.w = acc[ri*4+i][cj*4+3];
                *(float4*)(C + (size_t)row * N + col) = o;
            }
        }
}

// ---------------- pack: RMSNorm + rotary + [G,heads,L,hd] relayout ----------------
__global__ void pack_kernel(const float* __restrict__ rope,
                            const float* __restrict__ qnw,
                            const float* __restrict__ knw)
{
    int b = blockIdx.x;                 // g*LSEQ*HEADS + l*HEADS + h
    int h = b & (HEADS - 1);
    int rest = b >> 4;
    int l = rest % LSEQ;
    int g = rest / LSEQ;
    int d = threadIdx.x;                // 0..127

    int src;
    bool isvis = (l < LV);
    if (isvis) {
        int t   = l / 192;              // 192 = 12*16
        int rem = l - t * 192;
        int hl  = rem >> 4;
        int wl  = rem & 15;
        int hf  = (g >> 1) * 12 + hl;
        int wf  = (g & 1) * 16 + wl;
        src = (t * HDIM + hf) * WDIM + wf;
    } else {
        src = NV + (l - LV);
    }

    size_t off = (size_t)src * CDIM + (size_t)h * HD + d;
    float qv = g_q[off], kv = g_k[off], vv = g_v[off];

    float q2 = qv * qv, k2 = kv * kv;
#pragma unroll
    for (int o = 16; o > 0; o >>= 1) {
        q2 += __shfl_xor_sync(0xffffffffu, q2, o);
        k2 += __shfl_xor_sync(0xffffffffu, k2, o);
    }
    __shared__ float rq[4], rk[4];
    int warp = d >> 5;
    if ((d & 31) == 0) { rq[warp] = q2; rk[warp] = k2; }
    __syncthreads();
    float qs = rq[0] + rq[1] + rq[2] + rq[3];
    float ks = rk[0] + rk[1] + rk[2] + rk[3];

    float qn = qv * rsqrtf(qs * (1.0f / HD) + EPSV) * qnw[d];
    float kn = kv * rsqrtf(ks * (1.0f / HD) + EPSV) * knw[d];

    if (isvis) {
        __shared__ float shq[HD], shk[HD];
        shq[d] = qn; shk[d] = kn;
        __syncthreads();
        int i = d >> 1, j = d & 1;
        const float* rp = rope + (size_t)src * 256 + i * 4 + j * 2;
        float r0 = rp[0], r1 = rp[1];
        qn = r0 * shq[2*i] + r1 * shq[2*i+1];
        kn = r0 * shk[2*i] + r1 * shk[2*i+1];
    }

    size_t dst = (((size_t)(g * HEADS + h)) * LSEQ + l) * HD + d;
    g_Qp[dst] = qn; g_Kp[dst] = kn; g_Vp[dst] = vv;
}

// ---------------- row softmax over g_S (rows of length LSEQ) ----------------
__global__ void softmax_kernel()
{
    size_t row = blockIdx.x;
    float* p = g_S + row * (size_t)LSEQ;
    int tid = threadIdx.x;                 // 256 threads

    float vals[7];
    int cnt = 0;
    float m = -1e30f;
    for (int i = tid; i < LSEQ; i += 256) {
        float v = p[i];
        vals[cnt++] = v;
        m = fmaxf(m, v);
    }
    __shared__ float sh[8];
#pragma unroll
    for (int o = 16; o > 0; o >>= 1) m = fmaxf(m, __shfl_xor_sync(0xffffffffu, m, o));
    if ((tid & 31) == 0) sh[tid >> 5] = m;
    __syncthreads();
    float bm = sh[0];
#pragma unroll
    for (int w = 1; w < 8; w++) bm = fmaxf(bm, sh[w]);
    __syncthreads();

    float s = 0.f;
    for (int c = 0; c < cnt; c++) { float e = __expf(vals[c] - bm); vals[c] = e; s += e; }
#pragma unroll
    for (int o = 16; o > 0; o >>= 1) s += __shfl_xor_sync(0xffffffffu, s, o);
    if ((tid & 31) == 0) sh[tid >> 5] = s;
    __syncthreads();
    float tot = 0.f;
#pragma unroll
    for (int w = 0; w < 8; w++) tot += sh[w];
    float inv = 1.0f / tot;

    cnt = 0;
    for (int i = tid; i < LSEQ; i += 256) p[i] = vals[cnt++] * inv;
}

// ---------------- rebuild ctx rows (inverse group map; text = mean over groups) ---
__global__ void build_ctx()
{
    size_t idx = (size_t)blockIdx.x * blockDim.x + threadIdx.x;
    if (idx >= (size_t)NTOK * CDIM) return;
    int r = (int)(idx / CDIM);
    int c = (int)(idx - (size_t)r * CDIM);
    int h = c >> 7;
    int d = c & 127;

    float val;
    if (r < NV) {
        int t  = r / (HDIM * WDIM);
        int rm = r - t * (HDIM * WDIM);
        int hf = rm / WDIM;
        int wf = rm - hf * WDIM;
        int g  = (hf / 12) * 2 + (wf / 16);
        int l  = t * 192 + (hf % 12) * 16 + (wf & 15);
        val = g_O[(((size_t)(g * HEADS + h)) * LSEQ + l) * HD + d];
    } else {
        int tr = r - NV;
        size_t base = ((size_t)h * LSEQ + LV + tr) * HD + d;
        float s = 0.f;
#pragma unroll
        for (int g = 0; g < GNUM; g++)
            s += g_O[(size_t)g * HEADS * LSEQ * HD + base];
        val = 0.25f * s;
    }
    g_ctx[idx] = val;
}

// ---------------- launch ----------------
extern "C" void kernel_launch(void* const* d_in, const int* in_sizes, int n_in,
                              void* d_out, int out_size)
{
    const float* vis  = (const float*)d_in[0];
    const float* text = (const float*)d_in[1];
    const float* rope = (const float*)d_in[2];
    const float* Wq   = (const float*)d_in[3];
    const float* bq   = (const float*)d_in[4];
    const float* Wk   = (const float*)d_in[5];
    const float* bk   = (const float*)d_in[6];
    const float* Wv   = (const float*)d_in[7];
    const float* bv   = (const float*)d_in[8];
    const float* qnw  = (const float*)d_in[9];
    const float* knw  = (const float*)d_in[10];
    const float* Wo   = (const float*)d_in[11];
    const float* bo   = (const float*)d_in[12];
    float* out = (float*)d_out;

    float *x, *q, *k, *v, *Qp, *Kp, *Vp, *S, *O, *ctx;
    cudaGetSymbolAddress((void**)&x,   g_x);
    cudaGetSymbolAddress((void**)&q,   g_q);
    cudaGetSymbolAddress((void**)&k,   g_k);
    cudaGetSymbolAddress((void**)&v,   g_v);
    cudaGetSymbolAddress((void**)&Qp,  g_Qp);
    cudaGetSymbolAddress((void**)&Kp,  g_Kp);
    cudaGetSymbolAddress((void**)&Vp,  g_Vp);
    cudaGetSymbolAddress((void**)&S,   g_S);
    cudaGetSymbolAddress((void**)&O,   g_O);
    cudaGetSymbolAddress((void**)&ctx, g_ctx);

    // 1. concat inputs
    {
        size_t total4 = (size_t)NTOK * CDIM / 4;
        int blocks = (int)((total4 + 255) / 256);
        concat_kernel<<<blocks, 256>>>(vis, text);
    }

    // 2. QKV projections: [NTOK,C] @ W^T + b
    {
        dim3 grid(CDIM / 128, NTOK / 128, 1);
        sgemm_nt<<<grid, 256>>>(x, Wq, bq, q, NTOK, CDIM, CDIM, 1.0f, 0, 0, 0);
        sgemm_nt<<<grid, 256>>>(x, Wk, bk, k, NTOK, CDIM, CDIM, 1.0f, 0, 0, 0);
        sgemm_nt<<<grid, 256>>>(x, Wv, bv, v, NTOK, CDIM, CDIM, 1.0f, 0, 0, 0);
    }

    // 3. RMSNorm + rotary + relayout to [G,heads,L,hd]
    pack_kernel<<<GNUM * LSEQ * HEADS, HD>>>(rope, qnw, knw);

    // 4. scores S = scale * Q K^T, batched over 64 (g,h)
    {
        dim3 grid(LSEQ / 128, LSEQ / 128, GH);
        sgemm_nt<<<grid, 256>>>(Qp, Kp, nullptr, S, LSEQ, LSEQ, HD, SCALE,
                                (long long)LSEQ * HD, (long long)LSEQ * HD,
                                (long long)LSEQ * LSEQ);
    }

    // 5. softmax over rows
    softmax_kernel<<<GH * LSEQ, 256>>>();

    // 6. O = P @ V, batched
    {
        dim3 grid(HD / 128, LSEQ / 128, GH);
        sgemm_nn<<<grid, 256>>>(S, Vp, O, LSEQ, HD, LSEQ,
                                (long long)LSEQ * LSEQ, (long long)LSEQ * HD,
                                (long long)LSEQ * HD);
    }

    // 7. rebuild ctx rows (visual scatter + text mean)
    {
        size_t total = (size_t)NTOK * CDIM;
        int blocks = (int)((total + 255) / 256);
        build_ctx<<<blocks, 256>>>();
    }

    // 8. final projection to d_out
    {
        dim3 grid(CDIM / 128, NTOK / 128, 1);
        sgemm_nt<<<grid, 256>>>(ctx, Wo, bo, out, NTOK, CDIM, CDIM, 1.0f, 0, 0, 0);
    }
}

// round 5
// speedup vs baseline: 1.1100x; 1.1100x over previous
#include <cuda_runtime.h>
#include <cstdint>
#include <math.h>

// ---------------- fixed problem shapes ----------------
#define TDIM 8
#define HDIM 24
#define WDIM 32
#define CDIM 2048
#define LT   128
#define NV   (TDIM*HDIM*WDIM)   // 6144 visual tokens
#define NTOK (NV+LT)            // 6272
#define HEADS 16
#define HD    128
#define GNUM  4                 // gt=1, gh=2, gw=2
#define LV    (NV/GNUM)         // 1536
#define LSEQ  (LV+LT)           // 1664
#define GH    (GNUM*HEADS)      // 64
#define EPSV  1e-6f
#define SCALE 0.08838834764831845f   // 1/sqrt(128)

// GEMM tiling
#define BK     16
#define LDA    20                   // padded smem row (floats)
#define STG_F  (128*LDA)            // floats per stage per operand (2560)
#define NSTG   3
#define SMEM_BYTES (NSTG*STG_F*2*4) // 61440

// ---------------- scratch (device globals; no runtime allocs) ----------------
__device__ float g_x  [(size_t)NTOK*CDIM];
__device__ float g_q  [(size_t)NTOK*CDIM];
__device__ float g_k  [(size_t)NTOK*CDIM];
__device__ float g_v  [(size_t)NTOK*CDIM];
__device__ float g_Qp [(size_t)GH*LSEQ*HD];
__device__ float g_Kp [(size_t)GH*LSEQ*HD];
__device__ float g_Vp [(size_t)GH*HD*LSEQ];      // TRANSPOSED: [g,h,d,l]
__device__ float g_O  [(size_t)GH*LSEQ*HD];
__device__ float g_S  [(size_t)GH*LSEQ*LSEQ];    // 709 MB
__device__ float g_ctx[(size_t)NTOK*CDIM];

// ---------------- helpers ----------------
__device__ __forceinline__ float rna_tf32(float x) {
    uint32_t u;
    asm("cvt.rna.tf32.f32 %0, %1;" : "=r"(u) : "f"(x));
    return __uint_as_float(u);
}
// exact 2-term split: x = hi + lo + O(2^-22 x); hi,lo are tf32-representable
__device__ __forceinline__ void split_tf32(float x, uint32_t& hi, uint32_t& lo) {
    float h = rna_tf32(x);
    float l = rna_tf32(x - h);
    hi = __float_as_uint(h);
    lo = __float_as_uint(l);
}

__device__ __forceinline__ void cp_async16(uint32_t saddr, const void* gaddr) {
    asm volatile("cp.async.cg.shared.global [%0], [%1], 16;"
                 :: "r"(saddr), "l"(gaddr) : "memory");
}
__device__ __forceinline__ void cp_commit() {
    asm volatile("cp.async.commit_group;" ::: "memory");
}
__device__ __forceinline__ void cp_wait1() {
    asm volatile("cp.async.wait_group 1;" ::: "memory");
}

#define MMA_TF32(C0,C1,C2,C3, A0,A1,A2,A3, B0,B1)                         \
    asm volatile("mma.sync.aligned.m16n8k8.row.col.f32.tf32.tf32.f32 "    \
        "{%0,%1,%2,%3}, {%4,%5,%6,%7}, {%8,%9}, {%0,%1,%2,%3};"           \
        : "+f"(C0), "+f"(C1), "+f"(C2), "+f"(C3)                          \
        : "r"(A0), "r"(A1), "r"(A2), "r"(A3), "r"(B0), "r"(B1))

// =====================================================================
// 3xTF32 split-precision GEMM, NT: C[M,N] = alpha*A[M,K]*B[N,K]^T (+bias)
// Block tile 128x128, BK=16, 8 warps in 2x4 grid (64x32 per warp),
// 3-stage cp.async. fp32 inputs (split to tf32 hi/lo in-register).
// M,N multiples of 128, K multiple of 16. Batched via blockIdx.z.
// =====================================================================
__global__ void __launch_bounds__(256, 1)
mma_gemm_nt(const float* __restrict__ A, const float* __restrict__ B,
            const float* __restrict__ bias, float* __restrict__ C,
            int M, int N, int K, float alpha,
            long long strA, long long strB, long long strC)
{
    extern __shared__ float sh[];
    float* shA = sh;                 // NSTG * STG_F
    float* shB = sh + NSTG * STG_F;

    A += (long long)blockIdx.z * strA;
    B += (long long)blockIdx.z * strB;
    C += (long long)blockIdx.z * strC;

    const int tid  = threadIdx.x;
    const int lane = tid & 31;
    const int warp = tid >> 5;       // 0..7
    const int wm = warp >> 2;        // 0..1  (64 rows)
    const int wn = warp & 3;         // 0..3  (32 cols)
    const int gi = lane >> 2;        // 0..7
    const int ti = lane & 3;         // 0..3

    const float* Ab = A + (size_t)blockIdx.y * 128 * K;
    const float* Bb = B + (size_t)blockIdx.x * 128 * K;
    const uint32_t sA32 = (uint32_t)__cvta_generic_to_shared(shA);
    const uint32_t sB32 = (uint32_t)__cvta_generic_to_shared(shB);

    float acc[4][4][4];
#pragma unroll
    for (int mt = 0; mt < 4; mt++)
#pragma unroll
        for (int nt = 0; nt < 4; nt++)
#pragma unroll
            for (int r = 0; r < 4; r++) acc[mt][nt][r] = 0.f;

    float2 bb[4];
    if (bias) {
#pragma unroll
        for (int nt = 0; nt < 4; nt++)
            bb[nt] = *(const float2*)(bias + blockIdx.x * 128 + wn * 32 + nt * 8 + ti * 2);
    }

    const int nk = K / BK;

#define LOAD_STAGE(KT, SLOT)                                                   \
    {                                                                          \
        _Pragma("unroll")                                                      \
        for (int i = 0; i < 2; i++) {                                          \
            int idx = tid + i * 256;                                           \
            int row = idx >> 2, c4 = idx & 3;                                  \
            uint32_t so = (uint32_t)(((SLOT) * STG_F + row * LDA + c4 * 4) * 4);\
            cp_async16(sA32 + so, Ab + (size_t)row * K + (KT) * BK + c4 * 4);  \
            cp_async16(sB32 + so, Bb + (size_t)row * K + (KT) * BK + c4 * 4);  \
        }                                                                      \
    }

    LOAD_STAGE(0, 0); cp_commit();
    if (nk > 1) { LOAD_STAGE(1, 1); }
    cp_commit();

#pragma unroll 1
    for (int kt = 0; kt < nk; kt++) {
        cp_wait1();
        __syncthreads();
        if (kt + 2 < nk) { LOAD_STAGE(kt + 2, (kt + 2) % NSTG); }
        cp_commit();

        const float* pA = shA + (kt % NSTG) * STG_F;
        const float* pB = shB + (kt % NSTG) * STG_F;
#pragma unroll
        for (int ks = 0; ks < 2; ks++) {
            const int k0 = ks * 8 + ti;
            uint32_t ah[4][4], al[4][4];
#pragma unroll
            for (int mt = 0; mt < 4; mt++) {
                int r = wm * 64 + mt * 16 + gi;
                split_tf32(pA[r * LDA + k0],           ah[mt][0], al[mt][0]);
                split_tf32(pA[(r + 8) * LDA + k0],     ah[mt][1], al[mt][1]);
                split_tf32(pA[r * LDA + k0 + 4],       ah[mt][2], al[mt][2]);
                split_tf32(pA[(r + 8) * LDA + k0 + 4], ah[mt][3], al[mt][3]);
            }
            uint32_t bh[4][2], bl[4][2];
#pragma unroll
            for (int nt = 0; nt < 4; nt++) {
                int c = wn * 32 + nt * 8 + gi;
                split_tf32(pB[c * LDA + k0],     bh[nt][0], bl[nt][0]);
                split_tf32(pB[c * LDA + k0 + 4], bh[nt][1], bl[nt][1]);
            }
#pragma unroll
            for (int mt = 0; mt < 4; mt++)
#pragma unroll
                for (int nt = 0; nt < 4; nt++) {
                    // small cross terms first, dominant term last
                    MMA_TF32(acc[mt][nt][0], acc[mt][nt][1], acc[mt][nt][2], acc[mt][nt][3],
                             ah[mt][0], ah[mt][1], ah[mt][2], ah[mt][3],
                             bl[nt][0], bl[nt][1]);
                    MMA_TF32(acc[mt][nt][0], acc[mt][nt][1], acc[mt][nt][2], acc[mt][nt][3],
                             al[mt][0], al[mt][1], al[mt][2], al[mt][3],
                             bh[nt][0], bh[nt][1]);
                    MMA_TF32(acc[mt][nt][0], acc[mt][nt][1], acc[mt][nt][2], acc[mt][nt][3],
                             ah[mt][0], ah[mt][1], ah[mt][2], ah[mt][3],
                             bh[nt][0], bh[nt][1]);
                }
        }
    }

    // ---- epilogue ----
#pragma unroll
    for (int mt = 0; mt < 4; mt++) {
        int row0 = blockIdx.y * 128 + wm * 64 + mt * 16 + gi;
#pragma unroll
        for (int nt = 0; nt < 4; nt++) {
            int col = blockIdx.x * 128 + wn * 32 + nt * 8 + ti * 2;
            float bxv = bias ? bb[nt].x : 0.f;
            float byv = bias ? bb[nt].y : 0.f;
            float2 v0, v1;
            v0.x = alpha * acc[mt][nt][0] + bxv;
            v0.y = alpha * acc[mt][nt][1] + byv;
            v1.x = alpha * acc[mt][nt][2] + bxv;
            v1.y = alpha * acc[mt][nt][3] + byv;
            *(float2*)(C + (size_t)row0 * N + col)       = v0;
            *(float2*)(C + (size_t)(row0 + 8) * N + col) = v1;
        }
    }
}

// ---------------- concat visual+text ----------------
__global__ void concat_kernel(const float* __restrict__ vis, const float* __restrict__ text)
{
    size_t i4 = (size_t)blockIdx.x * blockDim.x + threadIdx.x;
    size_t total4 = (size_t)NTOK * CDIM / 4;
    if (i4 >= total4) return;
    size_t nv4 = (size_t)NV * CDIM / 4;
    float4 v;
    if (i4 < nv4) v = ((const float4*)vis)[i4];
    else          v = ((const float4*)text)[i4 - nv4];
    ((float4*)g_x)[i4] = v;
}

// ---------------- pack: RMSNorm + rotary + [G,heads,L,hd] relayout ------------
__global__ void pack_kernel(const float* __restrict__ rope,
                            const float* __restrict__ qnw,
                            const float* __restrict__ knw)
{
    int b = blockIdx.x;                 // g*LSEQ*HEADS + l*HEADS + h
    int h = b & (HEADS - 1);
    int rest = b >> 4;
    int l = rest % LSEQ;
    int g = rest / LSEQ;
    int d = threadIdx.x;                // 0..127

    int src;
    bool isvis = (l < LV);
    if (isvis) {
        int t   = l / 192;              // 192 = 12*16
        int rem = l - t * 192;
        int hl  = rem >> 4;
        int wl  = rem & 15;
        int hf  = (g >> 1) * 12 + hl;
        int wf  = (g & 1) * 16 + wl;
        src = (t * HDIM + hf) * WDIM + wf;
    } else {
        src = NV + (l - LV);
    }

    size_t off = (size_t)src * CDIM + (size_t)h * HD + d;
    float qv = g_q[off], kv = g_k[off], vv = g_v[off];

    float q2 = qv * qv, k2 = kv * kv;
#pragma unroll
    for (int o = 16; o > 0; o >>= 1) {
        q2 += __shfl_xor_sync(0xffffffffu, q2, o);
        k2 += __shfl_xor_sync(0xffffffffu, k2, o);
    }
    __shared__ float rq[4], rk[4];
    int warp = d >> 5;
    if ((d & 31) == 0) { rq[warp] = q2; rk[warp] = k2; }
    __syncthreads();
    float qs = rq[0] + rq[1] + rq[2] + rq[3];
    float ks = rk[0] + rk[1] + rk[2] + rk[3];

    float qn = qv * rsqrtf(qs * (1.0f / HD) + EPSV) * qnw[d];
    float kn = kv * rsqrtf(ks * (1.0f / HD) + EPSV) * knw[d];

    if (isvis) {
        __shared__ float shq[HD], shk[HD];
        shq[d] = qn; shk[d] = kn;
        __syncthreads();
        int i = d >> 1, j = d & 1;
        const float* rp = rope + (size_t)src * 256 + i * 4 + j * 2;
        float r0 = rp[0], r1 = rp[1];
        qn = r0 * shq[2*i] + r1 * shq[2*i+1];
        kn = r0 * shk[2*i] + r1 * shk[2*i+1];
    }

    size_t gh = (size_t)(g * HEADS + h);
    size_t dst = (gh * LSEQ + l) * HD + d;
    g_Qp[dst] = qn;
    g_Kp[dst] = kn;
    // V stored transposed: [gh, d, l]
    g_Vp[(gh * HD + d) * LSEQ + l] = vv;
}

// ---------------- row softmax over g_S (rows of length LSEQ) ----------------
__global__ void softmax_kernel()
{
    size_t row = blockIdx.x;
    float* p = g_S + row * (size_t)LSEQ;
    int tid = threadIdx.x;                 // 256 threads

    float vals[7];
    int cnt = 0;
    float m = -1e30f;
    for (int i = tid; i < LSEQ; i += 256) {
        float v = p[i];
        vals[cnt++] = v;
        m = fmaxf(m, v);
    }
    __shared__ float sh[8];
#pragma unroll
    for (int o = 16; o > 0; o >>= 1) m = fmaxf(m, __shfl_xor_sync(0xffffffffu, m, o));
    if ((tid & 31) == 0) sh[tid >> 5] = m;
    __syncthreads();
    float bm = sh[0];
#pragma unroll
    for (int w = 1; w < 8; w++) bm = fmaxf(bm, sh[w]);
    __syncthreads();

    float s = 0.f;
    for (int c = 0; c < cnt; c++) { float e = __expf(vals[c] - bm); vals[c] = e; s += e; }
#pragma unroll
    for (int o = 16; o > 0; o >>= 1) s += __shfl_xor_sync(0xffffffffu, s, o);
    if ((tid & 31) == 0) sh[tid >> 5] = s;
    __syncthreads();
    float tot = 0.f;
#pragma unroll
    for (int w = 0; w < 8; w++) tot += sh[w];
    float inv = 1.0f / tot;

    cnt = 0;
    for (int i = tid; i < LSEQ; i += 256) p[i] = vals[cnt++] * inv;
}

// ------- rebuild ctx rows (inverse group map; text = mean over groups) -------
__global__ void build_ctx()
{
    size_t idx = (size_t)blockIdx.x * blockDim.x + threadIdx.x;
    if (idx >= (size_t)NTOK * CDIM) return;
    int r = (int)(idx / CDIM);
    int c = (int)(idx - (size_t)r * CDIM);
    int h = c >> 7;
    int d = c & 127;

    float val;
    if (r < NV) {
        int t  = r / (HDIM * WDIM);
        int rm = r - t * (HDIM * WDIM);
        int hf = rm / WDIM;
        int wf = rm - hf * WDIM;
        int g  = (hf / 12) * 2 + (wf / 16);
        int l  = t * 192 + (hf % 12) * 16 + (wf & 15);
        val = g_O[(((size_t)(g * HEADS + h)) * LSEQ + l) * HD + d];
    } else {
        int tr = r - NV;
        size_t base = ((size_t)h * LSEQ + LV + tr) * HD + d;
        float s = 0.f;
#pragma unroll
        for (int g = 0; g < GNUM; g++)
            s += g_O[(size_t)g * HEADS * LSEQ * HD + base];
        val = 0.25f * s;
    }
    g_ctx[idx] = val;
}

// ---------------- launch ----------------
extern "C" void kernel_launch(void* const* d_in, const int* in_sizes, int n_in,
                              void* d_out, int out_size)
{
    const float* vis  = (const float*)d_in[0];
    const float* text = (const float*)d_in[1];
    const float* rope = (const float*)d_in[2];
    const float* Wq   = (const float*)d_in[3];
    const float* bq   = (const float*)d_in[4];
    const float* Wk   = (const float*)d_in[5];
    const float* bk   = (const float*)d_in[6];
    const float* Wv   = (const float*)d_in[7];
    const float* bv   = (const float*)d_in[8];
    const float* qnw  = (const float*)d_in[9];
    const float* knw  = (const float*)d_in[10];
    const float* Wo   = (const float*)d_in[11];
    const float* bo   = (const float*)d_in[12];
    float* out = (float*)d_out;

    float *x, *q, *k, *v, *Qp, *Kp, *Vp, *S, *O, *ctx;
    cudaGetSymbolAddress((void**)&x,   g_x);
    cudaGetSymbolAddress((void**)&q,   g_q);
    cudaGetSymbolAddress((void**)&k,   g_k);
    cudaGetSymbolAddress((void**)&v,   g_v);
    cudaGetSymbolAddress((void**)&Qp,  g_Qp);
    cudaGetSymbolAddress((void**)&Kp,  g_Kp);
    cudaGetSymbolAddress((void**)&Vp,  g_Vp);
    cudaGetSymbolAddress((void**)&S,   g_S);
    cudaGetSymbolAddress((void**)&O,   g_O);
    cudaGetSymbolAddress((void**)&ctx, g_ctx);

    cudaFuncSetAttribute(mma_gemm_nt, cudaFuncAttributeMaxDynamicSharedMemorySize, SMEM_BYTES);

    // 1. concat activations
    {
        size_t total4 = (size_t)NTOK * CDIM / 4;
        concat_kernel<<<(int)((total4 + 255) / 256), 256>>>(vis, text);
    }
    // 2. QKV projections (weights used directly; split happens in-kernel)
    {
        dim3 grid(CDIM / 128, NTOK / 128, 1);
        mma_gemm_nt<<<grid, 256, SMEM_BYTES>>>(x, Wq, bq, q, NTOK, CDIM, CDIM, 1.0f, 0, 0, 0);
        mma_gemm_nt<<<grid, 256, SMEM_BYTES>>>(x, Wk, bk, k, NTOK, CDIM, CDIM, 1.0f, 0, 0, 0);
        mma_gemm_nt<<<grid, 256, SMEM_BYTES>>>(x, Wv, bv, v, NTOK, CDIM, CDIM, 1.0f, 0, 0, 0);
    }
    // 3. RMSNorm + rotary + relayout (Q/K K-major, V transposed)
    pack_kernel<<<GNUM * LSEQ * HEADS, HD>>>(rope, qnw, knw);
    // 4. scores S = scale * Q K^T (batched over 64 g*h)
    {
        dim3 grid(LSEQ / 128, LSEQ / 128, GH);
        mma_gemm_nt<<<grid, 256, SMEM_BYTES>>>(Qp, Kp, nullptr, S, LSEQ, LSEQ, HD, SCALE,
                                               (long long)LSEQ * HD, (long long)LSEQ * HD,
                                               (long long)LSEQ * LSEQ);
    }
    // 5. softmax
    softmax_kernel<<<GH * LSEQ, 256>>>();
    // 6. O = P @ V  (V transposed -> NT form)
    {
        dim3 grid(HD / 128, LSEQ / 128, GH);
        mma_gemm_nt<<<grid, 256, SMEM_BYTES>>>(S, Vp, nullptr, O, LSEQ, HD, LSEQ, 1.0f,
                                               (long long)LSEQ * LSEQ, (long long)HD * LSEQ,
                                               (long long)LSEQ * HD);
    }
    // 7. rebuild ctx rows
    {
        size_t total = (size_t)NTOK * CDIM;
        build_ctx<<<(int)((total + 255) / 256), 256>>>();
    }
    // 8. final projection straight into d_out
    {
        dim3 grid(CDIM / 128, NTOK / 128, 1);
        mma_gemm_nt<<<grid, 256, SMEM_BYTES>>>(ctx, Wo, bo, out, NTOK, CDIM, CDIM, 1.0f, 0, 0, 0);
    }
}

// round 6
// speedup vs baseline: 1.1956x; 1.0771x over previous
#include <cuda_runtime.h>
#include <cstdint>
#include <math.h>

// ---------------- fixed problem shapes ----------------
#define TDIM 8
#define HDIM 24
#define WDIM 32
#define CDIM 2048
#define LT   128
#define NV   (TDIM*HDIM*WDIM)   // 6144 visual tokens
#define NTOK (NV+LT)            // 6272
#define HEADS 16
#define HD    128
#define GNUM  4                 // gt=1, gh=2, gw=2
#define LV    (NV/GNUM)         // 1536
#define LSEQ  (LV+LT)           // 1664
#define GH    (GNUM*HEADS)      // 64
#define EPSV  1e-6f
#define SCALE 0.08838834764831845f   // 1/sqrt(128)

// GEMM tiling
#define BK     16
#define LDA    20                   // padded smem row (floats)
#define STG_F  (128*LDA)            // floats per tile per stage (2560)
#define NSTG   3
#define SMEM3_BYTES (NSTG*STG_F*4*4) // 4 tiles/stage (Ah,Al,Bh,Bl) = 122880
#define SMEM1_BYTES (NSTG*STG_F*2*4) // 2 tiles/stage = 61440

// ---------------- scratch (device globals; no runtime allocs) ----------------
__device__ float g_xh [(size_t)NTOK*CDIM];
__device__ float g_xl [(size_t)NTOK*CDIM];
__device__ float g_q  [(size_t)NTOK*CDIM];
__device__ float g_k  [(size_t)NTOK*CDIM];
__device__ float g_v  [(size_t)NTOK*CDIM];
__device__ float g_Wqh[(size_t)CDIM*CDIM];
__device__ float g_Wql[(size_t)CDIM*CDIM];
__device__ float g_Wkh[(size_t)CDIM*CDIM];
__device__ float g_Wkl[(size_t)CDIM*CDIM];
__device__ float g_Wvh[(size_t)CDIM*CDIM];
__device__ float g_Wvl[(size_t)CDIM*CDIM];
__device__ float g_Woh[(size_t)CDIM*CDIM];
__device__ float g_Wol[(size_t)CDIM*CDIM];
__device__ float g_Qph[(size_t)GH*LSEQ*HD];
__device__ float g_Qpl[(size_t)GH*LSEQ*HD];
__device__ float g_Kph[(size_t)GH*LSEQ*HD];
__device__ float g_Kpl[(size_t)GH*LSEQ*HD];
__device__ float g_Vp [(size_t)GH*HD*LSEQ];      // TRANSPOSED [g,h,d,l], tf32-rounded
__device__ float g_O  [(size_t)GH*LSEQ*HD];
__device__ float g_S  [(size_t)GH*LSEQ*LSEQ];    // 709 MB
__device__ float g_ctxh[(size_t)NTOK*CDIM];
__device__ float g_ctxl[(size_t)NTOK*CDIM];

// ---------------- helpers ----------------
__device__ __forceinline__ float rna_tf32(float x) {
    uint32_t u;
    asm("cvt.rna.tf32.f32 %0, %1;" : "=r"(u) : "f"(x));
    return __uint_as_float(u);
}
__device__ __forceinline__ void split2(float x, float& hi, float& lo) {
    hi = rna_tf32(x);
    lo = rna_tf32(x - hi);
}

__device__ __forceinline__ void cp_async16(uint32_t saddr, const void* gaddr) {
    asm volatile("cp.async.cg.shared.global [%0], [%1], 16;"
                 :: "r"(saddr), "l"(gaddr) : "memory");
}
__device__ __forceinline__ void cp_commit() {
    asm volatile("cp.async.commit_group;" ::: "memory");
}
__device__ __forceinline__ void cp_wait1() {
    asm volatile("cp.async.wait_group 1;" ::: "memory");
}

#define MMA_TF32(C0,C1,C2,C3, A0,A1,A2,A3, B0,B1)                         \
    asm volatile("mma.sync.aligned.m16n8k8.row.col.f32.tf32.tf32.f32 "    \
        "{%0,%1,%2,%3}, {%4,%5,%6,%7}, {%8,%9}, {%0,%1,%2,%3};"           \
        : "+f"(C0), "+f"(C1), "+f"(C2), "+f"(C3)                          \
        : "r"(A0), "r"(A1), "r"(A2), "r"(A3), "r"(B0), "r"(B1))

// =====================================================================
// 3xTF32 GEMM with PRE-SPLIT hi/lo operands, NT:
//   C = alpha * (Ah+Al)(Bh+Bl)^T (+bias), dropping Al*Bl.
// Block 128x128, BK=16, 8 warps 2x4 (64x32/warp), 3-stage cp.async.
// =====================================================================
__global__ void __launch_bounds__(256, 1)
mma_gemm_nt3(const float* __restrict__ Ah, const float* __restrict__ Al,
             const float* __restrict__ Bh, const float* __restrict__ Bl,
             const float* __restrict__ bias, float* __restrict__ C,
             int M, int N, int K, float alpha,
             long long strA, long long strB, long long strC)
{
    extern __shared__ float sh[];

    Ah += (long long)blockIdx.z * strA;  Al += (long long)blockIdx.z * strA;
    Bh += (long long)blockIdx.z * strB;  Bl += (long long)blockIdx.z * strB;
    C  += (long long)blockIdx.z * strC;

    const int tid  = threadIdx.x;
    const int lane = tid & 31;
    const int warp = tid >> 5;       // 0..7
    const int wm = warp >> 2;        // 0..1
    const int wn = warp & 3;         // 0..3
    const int gi = lane >> 2;        // 0..7
    const int ti = lane & 3;         // 0..3

    const size_t arow = (size_t)blockIdx.y * 128;
    const size_t brow = (size_t)blockIdx.x * 128;
    const float* Ahb = Ah + arow * K;
    const float* Alb = Al + arow * K;
    const float* Bhb = Bh + brow * K;
    const float* Blb = Bl + brow * K;
    const uint32_t sbase = (uint32_t)__cvta_generic_to_shared(sh);

    float acc[4][4][4];
#pragma unroll
    for (int mt = 0; mt < 4; mt++)
#pragma unroll
        for (int nt = 0; nt < 4; nt++)
#pragma unroll
            for (int r = 0; r < 4; r++) acc[mt][nt][r] = 0.f;

    float2 bb[4];
    if (bias) {
#pragma unroll
        for (int nt = 0; nt < 4; nt++)
            bb[nt] = *(const float2*)(bias + blockIdx.x * 128 + wn * 32 + nt * 8 + ti * 2);
    }

    const int nk = K / BK;

#define LOAD_STAGE3(KT, SLOT)                                                    \
    {                                                                            \
        _Pragma("unroll")                                                        \
        for (int i = 0; i < 2; i++) {                                            \
            int idx = tid + i * 256;                                             \
            int row = idx >> 2, c4 = idx & 3;                                    \
            size_t go = (size_t)row * K + (KT) * BK + c4 * 4;                    \
            uint32_t so = sbase + (uint32_t)(((SLOT)*4*STG_F + row*LDA + c4*4)*4);\
            cp_async16(so,               Ahb + go);                              \
            cp_async16(so +   STG_F * 4, Alb + go);                              \
            cp_async16(so + 2*STG_F * 4, Bhb + go);                              \
            cp_async16(so + 3*STG_F * 4, Blb + go);                              \
        }                                                                        \
    }

    LOAD_STAGE3(0, 0); cp_commit();
    if (nk > 1) { LOAD_STAGE3(1, 1); }
    cp_commit();

#pragma unroll 1
    for (int kt = 0; kt < nk; kt++) {
        cp_wait1();
        __syncthreads();
        if (kt + 2 < nk) { LOAD_STAGE3(kt + 2, (kt + 2) % NSTG); }
        cp_commit();

        const float* pAh = sh + (kt % NSTG) * 4 * STG_F;
        const float* pAl = pAh + STG_F;
        const float* pBh = pAh + 2 * STG_F;
        const float* pBl = pAh + 3 * STG_F;
#pragma unroll
        for (int ks = 0; ks < 2; ks++) {
            const int k0 = ks * 8 + ti;
            uint32_t ah[4][4], al[4][4];
#pragma unroll
            for (int mt = 0; mt < 4; mt++) {
                int r = wm * 64 + mt * 16 + gi;
                ah[mt][0] = __float_as_uint(pAh[r * LDA + k0]);
                ah[mt][1] = __float_as_uint(pAh[(r + 8) * LDA + k0]);
                ah[mt][2] = __float_as_uint(pAh[r * LDA + k0 + 4]);
                ah[mt][3] = __float_as_uint(pAh[(r + 8) * LDA + k0 + 4]);
                al[mt][0] = __float_as_uint(pAl[r * LDA + k0]);
                al[mt][1] = __float_as_uint(pAl[(r + 8) * LDA + k0]);
                al[mt][2] = __float_as_uint(pAl[r * LDA + k0 + 4]);
                al[mt][3] = __float_as_uint(pAl[(r + 8) * LDA + k0 + 4]);
            }
            uint32_t bh[4][2], bl[4][2];
#pragma unroll
            for (int nt = 0; nt < 4; nt++) {
                int c = wn * 32 + nt * 8 + gi;
                bh[nt][0] = __float_as_uint(pBh[c * LDA + k0]);
                bh[nt][1] = __float_as_uint(pBh[c * LDA + k0 + 4]);
                bl[nt][0] = __float_as_uint(pBl[c * LDA + k0]);
                bl[nt][1] = __float_as_uint(pBl[c * LDA + k0 + 4]);
            }
            // pass 1: Ah x Bl  (16 independent MMAs)
#pragma unroll
            for (int mt = 0; mt < 4; mt++)
#pragma unroll
                for (int nt = 0; nt < 4; nt++)
                    MMA_TF32(acc[mt][nt][0], acc[mt][nt][1], acc[mt][nt][2], acc[mt][nt][3],
                             ah[mt][0], ah[mt][1], ah[mt][2], ah[mt][3],
                             bl[nt][0], bl[nt][1]);
            // pass 2: Al x Bh
#pragma unroll
            for (int mt = 0; mt < 4; mt++)
#pragma unroll
                for (int nt = 0; nt < 4; nt++)
                    MMA_TF32(acc[mt][nt][0], acc[mt][nt][1], acc[mt][nt][2], acc[mt][nt][3],
                             al[mt][0], al[mt][1], al[mt][2], al[mt][3],
                             bh[nt][0], bh[nt][1]);
            // pass 3: Ah x Bh
#pragma unroll
            for (int mt = 0; mt < 4; mt++)
#pragma unroll
                for (int nt = 0; nt < 4; nt++)
                    MMA_TF32(acc[mt][nt][0], acc[mt][nt][1], acc[mt][nt][2], acc[mt][nt][3],
                             ah[mt][0], ah[mt][1], ah[mt][2], ah[mt][3],
                             bh[nt][0], bh[nt][1]);
        }
    }

#pragma unroll
    for (int mt = 0; mt < 4; mt++) {
        int row0 = blockIdx.y * 128 + wm * 64 + mt * 16 + gi;
#pragma unroll
        for (int nt = 0; nt < 4; nt++) {
            int col = blockIdx.x * 128 + wn * 32 + nt * 8 + ti * 2;
            float bxv = bias ? bb[nt].x : 0.f;
            float byv = bias ? bb[nt].y : 0.f;
            float2 v0, v1;
            v0.x = alpha * acc[mt][nt][0] + bxv;
            v0.y = alpha * acc[mt][nt][1] + byv;
            v1.x = alpha * acc[mt][nt][2] + bxv;
            v1.y = alpha * acc[mt][nt][3] + byv;
            *(float2*)(C + (size_t)row0 * N + col)       = v0;
            *(float2*)(C + (size_t)(row0 + 8) * N + col) = v1;
        }
    }
}

// =====================================================================
// 1xTF32 GEMM (inputs already tf32-rounded), NT. Same tiling; occ 2.
// =====================================================================
__global__ void __launch_bounds__(256, 2)
mma_gemm_nt1(const float* __restrict__ A, const float* __restrict__ B,
             float* __restrict__ C, int M, int N, int K, float alpha,
             long long strA, long long strB, long long strC)
{
    extern __shared__ float sh[];
    float* shA = sh;
    float* shB = sh + NSTG * STG_F;

    A += (long long)blockIdx.z * strA;
    B += (long long)blockIdx.z * strB;
    C += (long long)blockIdx.z * strC;

    const int tid  = threadIdx.x;
    const int lane = tid & 31;
    const int warp = tid >> 5;
    const int wm = warp >> 2;
    const int wn = warp & 3;
    const int gi = lane >> 2;
    const int ti = lane & 3;

    const float* Ab = A + (size_t)blockIdx.y * 128 * K;
    const float* Bb = B + (size_t)blockIdx.x * 128 * K;
    const uint32_t sA32 = (uint32_t)__cvta_generic_to_shared(shA);
    const uint32_t sB32 = (uint32_t)__cvta_generic_to_shared(shB);

    float acc[4][4][4];
#pragma unroll
    for (int mt = 0; mt < 4; mt++)
#pragma unroll
        for (int nt = 0; nt < 4; nt++)
#pragma unroll
            for (int r = 0; r < 4; r++) acc[mt][nt][r] = 0.f;

    const int nk = K / BK;

#define LOAD_STAGE1(KT, SLOT)                                                  \
    {                                                                          \
        _Pragma("unroll")                                                      \
        for (int i = 0; i < 2; i++) {                                          \
            int idx = tid + i * 256;                                           \
            int row = idx >> 2, c4 = idx & 3;                                  \
            size_t go = (size_t)row * K + (KT) * BK + c4 * 4;                  \
            uint32_t so = (uint32_t)(((SLOT) * STG_F + row * LDA + c4 * 4) * 4);\
            cp_async16(sA32 + so, Ab + go);                                    \
            cp_async16(sB32 + so, Bb + go);                                    \
        }                                                                      \
    }

    LOAD_STAGE1(0, 0); cp_commit();
    if (nk > 1) { LOAD_STAGE1(1, 1); }
    cp_commit();

#pragma unroll 1
    for (int kt = 0; kt < nk; kt++) {
        cp_wait1();
        __syncthreads();
        if (kt + 2 < nk) { LOAD_STAGE1(kt + 2, (kt + 2) % NSTG); }
        cp_commit();

        const float* pA = shA + (kt % NSTG) * STG_F;
        const float* pB = shB + (kt % NSTG) * STG_F;
#pragma unroll
        for (int ks = 0; ks < 2; ks++) {
            const int k0 = ks * 8 + ti;
            uint32_t af[4][4];
#pragma unroll
            for (int mt = 0; mt < 4; mt++) {
                int r = wm * 64 + mt * 16 + gi;
                af[mt][0] = __float_as_uint(pA[r * LDA + k0]);
                af[mt][1] = __float_as_uint(pA[(r + 8) * LDA + k0]);
                af[mt][2] = __float_as_uint(pA[r * LDA + k0 + 4]);
                af[mt][3] = __float_as_uint(pA[(r + 8) * LDA + k0 + 4]);
            }
            uint32_t bf[4][2];
#pragma unroll
            for (int nt = 0; nt < 4; nt++) {
                int c = wn * 32 + nt * 8 + gi;
                bf[nt][0] = __float_as_uint(pB[c * LDA + k0]);
                bf[nt][1] = __float_as_uint(pB[c * LDA + k0 + 4]);
            }
#pragma unroll
            for (int mt = 0; mt < 4; mt++)
#pragma unroll
                for (int nt = 0; nt < 4; nt++)
                    MMA_TF32(acc[mt][nt][0], acc[mt][nt][1], acc[mt][nt][2], acc[mt][nt][3],
                             af[mt][0], af[mt][1], af[mt][2], af[mt][3],
                             bf[nt][0], bf[nt][1]);
        }
    }

#pragma unroll
    for (int mt = 0; mt < 4; mt++) {
        int row0 = blockIdx.y * 128 + wm * 64 + mt * 16 + gi;
#pragma unroll
        for (int nt = 0; nt < 4; nt++) {
            int col = blockIdx.x * 128 + wn * 32 + nt * 8 + ti * 2;
            float2 v0, v1;
            v0.x = alpha * acc[mt][nt][0];
            v0.y = alpha * acc[mt][nt][1];
            v1.x = alpha * acc[mt][nt][2];
            v1.y = alpha * acc[mt][nt][3];
            *(float2*)(C + (size_t)row0 * N + col)       = v0;
            *(float2*)(C + (size_t)(row0 + 8) * N + col) = v1;
        }
    }
}

// ---------------- concat visual+text -> hi/lo split ----------------
__global__ void concat_kernel(const float* __restrict__ vis, const float* __restrict__ text)
{
    size_t i4 = (size_t)blockIdx.x * blockDim.x + threadIdx.x;
    size_t total4 = (size_t)NTOK * CDIM / 4;
    if (i4 >= total4) return;
    size_t nv4 = (size_t)NV * CDIM / 4;
    float4 v;
    if (i4 < nv4) v = ((const float4*)vis)[i4];
    else          v = ((const float4*)text)[i4 - nv4];
    float4 h, l;
    split2(v.x, h.x, l.x); split2(v.y, h.y, l.y);
    split2(v.z, h.z, l.z); split2(v.w, h.w, l.w);
    ((float4*)g_xh)[i4] = h;
    ((float4*)g_xl)[i4] = l;
}

// ---------------- split a weight matrix into hi/lo ----------------
__global__ void wsplit_kernel(const float* __restrict__ src,
                              float* __restrict__ dsth, float* __restrict__ dstl, int n4)
{
    int i = blockIdx.x * 256 + threadIdx.x;
    if (i >= n4) return;
    float4 v = ((const float4*)src)[i];
    float4 h, l;
    split2(v.x, h.x, l.x); split2(v.y, h.y, l.y);
    split2(v.z, h.z, l.z); split2(v.w, h.w, l.w);
    ((float4*)dsth)[i] = h;
    ((float4*)dstl)[i] = l;
}

// ------ pack: RMSNorm + rotary + relayout; Q/K hi/lo, V rounded transposed ----
__global__ void pack_kernel(const float* __restrict__ rope,
                            const float* __restrict__ qnw,
                            const float* __restrict__ knw)
{
    int b = blockIdx.x;                 // g*LSEQ*HEADS + l*HEADS + h
    int h = b & (HEADS - 1);
    int rest = b >> 4;
    int l = rest % LSEQ;
    int g = rest / LSEQ;
    int d = threadIdx.x;                // 0..127

    int src;
    bool isvis = (l < LV);
    if (isvis) {
        int t   = l / 192;              // 192 = 12*16
        int rem = l - t * 192;
        int hl  = rem >> 4;
        int wl  = rem & 15;
        int hf  = (g >> 1) * 12 + hl;
        int wf  = (g & 1) * 16 + wl;
        src = (t * HDIM + hf) * WDIM + wf;
    } else {
        src = NV + (l - LV);
    }

    size_t off = (size_t)src * CDIM + (size_t)h * HD + d;
    float qv = g_q[off], kv = g_k[off], vv = g_v[off];

    float q2 = qv * qv, k2 = kv * kv;
#pragma unroll
    for (int o = 16; o > 0; o >>= 1) {
        q2 += __shfl_xor_sync(0xffffffffu, q2, o);
        k2 += __shfl_xor_sync(0xffffffffu, k2, o);
    }
    __shared__ float rq[4], rk[4];
    int warp = d >> 5;
    if ((d & 31) == 0) { rq[warp] = q2; rk[warp] = k2; }
    __syncthreads();
    float qs = rq[0] + rq[1] + rq[2] + rq[3];
    float ks = rk[0] + rk[1] + rk[2] + rk[3];

    float qn = qv * rsqrtf(qs * (1.0f / HD) + EPSV) * qnw[d];
    float kn = kv * rsqrtf(ks * (1.0f / HD) + EPSV) * knw[d];

    if (isvis) {
        __shared__ float shq[HD], shk[HD];
        shq[d] = qn; shk[d] = kn;
        __syncthreads();
        int i = d >> 1, j = d & 1;
        const float* rp = rope + (size_t)src * 256 + i * 4 + j * 2;
        float r0 = rp[0], r1 = rp[1];
        qn = r0 * shq[2*i] + r1 * shq[2*i+1];
        kn = r0 * shk[2*i] + r1 * shk[2*i+1];
    }

    size_t gh = (size_t)(g * HEADS + h);
    size_t dst = (gh * LSEQ + l) * HD + d;
    float hh, ll;
    split2(qn, hh, ll); g_Qph[dst] = hh; g_Qpl[dst] = ll;
    split2(kn, hh, ll); g_Kph[dst] = hh; g_Kpl[dst] = ll;
    // V stored transposed [gh, d, l], rounded for 1xtf32 PV
    g_Vp[(gh * HD + d) * LSEQ + l] = rna_tf32(vv);
}

// ------ row softmax over g_S; output rounded to tf32 for 1xtf32 PV ----------
__global__ void softmax_kernel()
{
    size_t row = blockIdx.x;
    float* p = g_S + row * (size_t)LSEQ;
    int tid = threadIdx.x;                 // 256 threads

    float vals[7];
    int cnt = 0;
    float m = -1e30f;
    for (int i = tid; i < LSEQ; i += 256) {
        float v = p[i];
        vals[cnt++] = v;
        m = fmaxf(m, v);
    }
    __shared__ float sh[8];
#pragma unroll
    for (int o = 16; o > 0; o >>= 1) m = fmaxf(m, __shfl_xor_sync(0xffffffffu, m, o));
    if ((tid & 31) == 0) sh[tid >> 5] = m;
    __syncthreads();
    float bm = sh[0];
#pragma unroll
    for (int w = 1; w < 8; w++) bm = fmaxf(bm, sh[w]);
    __syncthreads();

    float s = 0.f;
    for (int c = 0; c < cnt; c++) { float e = __expf(vals[c] - bm); vals[c] = e; s += e; }
#pragma unroll
    for (int o = 16; o > 0; o >>= 1) s += __shfl_xor_sync(0xffffffffu, s, o);
    if ((tid & 31) == 0) sh[tid >> 5] = s;
    __syncthreads();
    float tot = 0.f;
#pragma unroll
    for (int w = 0; w < 8; w++) tot += sh[w];
    float inv = 1.0f / tot;

    cnt = 0;
    for (int i = tid; i < LSEQ; i += 256) p[i] = rna_tf32(vals[cnt++] * inv);
}

// ------- rebuild ctx rows -> hi/lo (visual scatter + text mean) --------------
__global__ void build_ctx()
{
    size_t idx = (size_t)blockIdx.x * blockDim.x + threadIdx.x;
    if (idx >= (size_t)NTOK * CDIM) return;
    int r = (int)(idx / CDIM);
    int c = (int)(idx - (size_t)r * CDIM);
    int h = c >> 7;
    int d = c & 127;

    float val;
    if (r < NV) {
        int t  = r / (HDIM * WDIM);
        int rm = r - t * (HDIM * WDIM);
        int hf = rm / WDIM;
        int wf = rm - hf * WDIM;
        int g  = (hf / 12) * 2 + (wf / 16);
        int l  = t * 192 + (hf % 12) * 16 + (wf & 15);
        val = g_O[(((size_t)(g * HEADS + h)) * LSEQ + l) * HD + d];
    } else {
        int tr = r - NV;
        size_t base = ((size_t)h * LSEQ + LV + tr) * HD + d;
        float s = 0.f;
#pragma unroll
        for (int g = 0; g < GNUM; g++)
            s += g_O[(size_t)g * HEADS * LSEQ * HD + base];
        val = 0.25f * s;
    }
    float hh, ll;
    split2(val, hh, ll);
    g_ctxh[idx] = hh;
    g_ctxl[idx] = ll;
}

// ---------------- launch ----------------
extern "C" void kernel_launch(void* const* d_in, const int* in_sizes, int n_in,
                              void* d_out, int out_size)
{
    const float* vis  = (const float*)d_in[0];
    const float* text = (const float*)d_in[1];
    const float* rope = (const float*)d_in[2];
    const float* Wq   = (const float*)d_in[3];
    const float* bq   = (const float*)d_in[4];
    const float* Wk   = (const float*)d_in[5];
    const float* bk   = (const float*)d_in[6];
    const float* Wv   = (const float*)d_in[7];
    const float* bv   = (const float*)d_in[8];
    const float* qnw  = (const float*)d_in[9];
    const float* knw  = (const float*)d_in[10];
    const float* Wo   = (const float*)d_in[11];
    const float* bo   = (const float*)d_in[12];
    float* out = (float*)d_out;

    float *xh, *xl, *q, *k, *v, *S, *O, *Vp, *ctxh, *ctxl;
    float *Qph, *Qpl, *Kph, *Kpl;
    float *wqh, *wql, *wkh, *wkl, *wvh, *wvl, *woh, *wol;
    cudaGetSymbolAddress((void**)&xh,  g_xh);
    cudaGetSymbolAddress((void**)&xl,  g_xl);
    cudaGetSymbolAddress((void**)&q,   g_q);
    cudaGetSymbolAddress((void**)&k,   g_k);
    cudaGetSymbolAddress((void**)&v,   g_v);
    cudaGetSymbolAddress((void**)&Qph, g_Qph);
    cudaGetSymbolAddress((void**)&Qpl, g_Qpl);
    cudaGetSymbolAddress((void**)&Kph, g_Kph);
    cudaGetSymbolAddress((void**)&Kpl, g_Kpl);
    cudaGetSymbolAddress((void**)&Vp,  g_Vp);
    cudaGetSymbolAddress((void**)&S,   g_S);
    cudaGetSymbolAddress((void**)&O,   g_O);
    cudaGetSymbolAddress((void**)&ctxh, g_ctxh);
    cudaGetSymbolAddress((void**)&ctxl, g_ctxl);
    cudaGetSymbolAddress((void**)&wqh, g_Wqh);
    cudaGetSymbolAddress((void**)&wql, g_Wql);
    cudaGetSymbolAddress((void**)&wkh, g_Wkh);
    cudaGetSymbolAddress((void**)&wkl, g_Wkl);
    cudaGetSymbolAddress((void**)&wvh, g_Wvh);
    cudaGetSymbolAddress((void**)&wvl, g_Wvl);
    cudaGetSymbolAddress((void**)&woh, g_Woh);
    cudaGetSymbolAddress((void**)&wol, g_Wol);

    cudaFuncSetAttribute(mma_gemm_nt3, cudaFuncAttributeMaxDynamicSharedMemorySize, SMEM3_BYTES);
    cudaFuncSetAttribute(mma_gemm_nt1, cudaFuncAttributeMaxDynamicSharedMemorySize, SMEM1_BYTES);

    // 1. concat + split activations; split weights
    {
        size_t total4 = (size_t)NTOK * CDIM / 4;
        concat_kernel<<<(int)((total4 + 255) / 256), 256>>>(vis, text);
        int n4 = CDIM * CDIM / 4;
        int blocks = (n4 + 255) / 256;
        wsplit_kernel<<<blocks, 256>>>(Wq, wqh, wql, n4);
        wsplit_kernel<<<blocks, 256>>>(Wk, wkh, wkl, n4);
        wsplit_kernel<<<blocks, 256>>>(Wv, wvh, wvl, n4);
        wsplit_kernel<<<blocks, 256>>>(Wo, woh, wol, n4);
    }
    // 2. QKV projections (3xtf32, pre-split operands)
    {
        dim3 grid(CDIM / 128, NTOK / 128, 1);
        mma_gemm_nt3<<<grid, 256, SMEM3_BYTES>>>(xh, xl, wqh, wql, bq, q, NTOK, CDIM, CDIM, 1.0f, 0, 0, 0);
        mma_gemm_nt3<<<grid, 256, SMEM3_BYTES>>>(xh, xl, wkh, wkl, bk, k, NTOK, CDIM, CDIM, 1.0f, 0, 0, 0);
        mma_gemm_nt3<<<grid, 256, SMEM3_BYTES>>>(xh, xl, wvh, wvl, bv, v, NTOK, CDIM, CDIM, 1.0f, 0, 0, 0);
    }
    // 3. RMSNorm + rotary + relayout
    pack_kernel<<<GNUM * LSEQ * HEADS, HD>>>(rope, qnw, knw);
    // 4. scores S = scale * Q K^T (3xtf32, batched over 64)
    {
        dim3 grid(LSEQ / 128, LSEQ / 128, GH);
        mma_gemm_nt3<<<grid, 256, SMEM3_BYTES>>>(Qph, Qpl, Kph, Kpl, nullptr, S, LSEQ, LSEQ, HD, SCALE,
                                                 (long long)LSEQ * HD, (long long)LSEQ * HD,
                                                 (long long)LSEQ * LSEQ);
    }
    // 5. softmax (rounds P to tf32)
    softmax_kernel<<<GH * LSEQ, 256>>>();
    // 6. O = P @ V (1xtf32; inputs pre-rounded)
    {
        dim3 grid(HD / 128, LSEQ / 128, GH);
        mma_gemm_nt1<<<grid, 256, SMEM1_BYTES>>>(S, Vp, O, LSEQ, HD, LSEQ, 1.0f,
                                                 (long long)LSEQ * LSEQ, (long long)HD * LSEQ,
                                                 (long long)LSEQ * HD);
    }
    // 7. rebuild ctx rows (hi/lo split)
    {
        size_t total = (size_t)NTOK * CDIM;
        build_ctx<<<(int)((total + 255) / 256), 256>>>();
    }
    // 8. final projection straight into d_out (3xtf32)
    {
        dim3 grid(CDIM / 128, NTOK / 128, 1);
        mma_gemm_nt3<<<grid, 256, SMEM3_BYTES>>>(ctxh, ctxl, woh, wol, bo, out, NTOK, CDIM, CDIM, 1.0f, 0, 0, 0);
    }
}